// round 4
// baseline (speedup 1.0000x reference)
#include <cuda_runtime.h>
#include <math.h>

#define NB     32
#define HH     128
#define WW     128
#define CC     80
#define CHN    84
#define KTOP   100
#define CAP    262144
#define SORTN  2048
#define NBINS2 16384

#define NBLK   296
#define THR    320
#define NWARP  10
#define WCAP   384
#define RING   5
#define ROWF4  680         /* 34 x * 20 float4 */
#define NTILES 1024        /* 4 x-tiles * 8 y-tiles * 32 batches */
#define DYNSMEM 85160      /* 5*10880*... ring 54400 + wbuf 30720 + wcnt 40 */

__device__ unsigned g_ticket, g_arrive, g_done;
__device__ unsigned g_count[NB];
__device__ unsigned long long g_cand[NB][CAP];

__device__ __forceinline__ unsigned su32(const void* p) {
    return (unsigned)__cvta_generic_to_shared(p);
}

__global__ void __launch_bounds__(THR, 2) fused_kernel(const float* __restrict__ det,
                                                       float* __restrict__ out) {
    extern __shared__ __align__(16) char dsm[];
    // ---- phase-1 layout ----
    float* ring = (float*)dsm;                                        // RING*2720 f
    unsigned long long* wbuf = (unsigned long long*)(dsm + RING * 10880);
    unsigned* wcnt = (unsigned*)(wbuf + NWARP * WCAP);
    // ---- phase-2 overlay ----
    unsigned* hist = (unsigned*)dsm;                                  // 16384
    unsigned* csA  = hist + NBINS2;                                   // 256
    unsigned* csB  = csA + 256;                                       // 256+2 pad
    unsigned long long* sel = (unsigned long long*)(csB + 258);       // 2048 (8B-aligned)

    __shared__ unsigned s_tile;
    __shared__ int s_cc, s_n;
    __shared__ unsigned s_above, s_T;

    const int tid  = threadIdx.x;
    const int wid  = tid >> 5, lane = tid & 31;
    const int c    = tid % 80;
    const int xbase = (tid / 80) * 8;

    if (lane == 0) wcnt[wid] = 0u;
    __syncwarp();

    // ================= PHASE 1: peak detect (work-stealing tiles) =============
    for (;;) {
        if (tid == 0) s_tile = atomicAdd(&g_ticket, 1u);
        __syncthreads();                       // also fences ring reuse across tiles
        unsigned tile = s_tile;
        if (tile >= NTILES) break;
        const int b  = tile >> 5;
        const int x0 = (tile & 3) * 32;
        const int y0 = ((tile >> 2) & 7) * 16;

        auto issue_row = [&](int ry) {
            int gy = min(HH - 1, max(0, y0 - 1 + ry));   // clamp == SAME pad
            const float* rp = det + (size_t)(b * HH + gy) * WW * CHN;
            float* slot = ring + (ry % RING) * 2720;
            #pragma unroll
            for (int t = 0; t < 3; t++) {
                int i = tid + t * THR;
                if (i < ROWF4) {
                    int xl = i / 20, q = i - xl * 20;
                    int gx = min(WW - 1, max(0, x0 - 1 + xl));
                    asm volatile("cp.async.cg.shared.global [%0], [%1], 16;"
                                 :: "r"(su32(slot + xl * 80 + q * 4)),
                                    "l"(rp + gx * CHN + q * 4));
                }
            }
            asm volatile("cp.async.commit_group;");
        };

        issue_row(0); issue_row(1); issue_row(2);

        for (int y = 0; y < 16; y++) {
            if (y + 3 <= 17) issue_row(y + 3);
            else asm volatile("cp.async.commit_group;");
            asm volatile("cp.async.wait_group 1;");      // rows <= y+2 resident
            __syncthreads();

            const float* r0 = ring + ( y      % RING) * 2720;
            const float* r1 = ring + ((y + 1) % RING) * 2720;
            const float* r2 = ring + ((y + 2) % RING) * 2720;
            const int gy = y0 + y;

            float ctrC, ctrN, junk;
            auto vmax3 = [&](int t, float& ctr) {
                float a0 = r0[t * 80 + c];
                float a1 = r1[t * 80 + c];
                float a2 = r2[t * 80 + c];
                ctr = a1;
                return fmaxf(a0, fmaxf(a1, a2));
            };
            float vmL = vmax3(xbase, junk);
            float vmC = vmax3(xbase + 1, ctrC);
            #pragma unroll
            for (int k = 0; k < 8; k++) {
                float vmN = vmax3(xbase + k + 2, ctrN);
                float m   = fmaxf(vmL, fmaxf(vmC, vmN));
                float ctr = ctrC;
                float d   = m - ctr;
                float amax = fmaxf(fabsf(ctr), fabsf(m));
                if (d < 0.0421f || amax >= 6.0f) {       // needs-attention screen
                    bool cand;
                    if (d < 3.6e-4f) {
                        cand = true;                     // sig-diff <= d/4 < 1e-4
                    } else {
                        float s  = 1.0f / (1.0f + expf(-ctr));
                        float sm = 1.0f / (1.0f + expf(-m));
                        cand = fabsf(s - sm) < 1e-4f;
                    }
                    if (cand) {
                        unsigned bits   = __float_as_uint(m);
                        unsigned mapped = (bits & 0x80000000u) ? ~bits
                                                               : (bits | 0x80000000u);
                        unsigned idx = ((unsigned)gy * WW
                                      + (unsigned)(x0 + xbase + k)) * CC + (unsigned)c;
                        unsigned long long key = ((unsigned long long)mapped << 21)
                                               | (unsigned long long)(0x1FFFFFu - idx);
                        unsigned p = atomicAdd(&wcnt[wid], 1u);   // warp-local ATOMS
                        if (p < WCAP) wbuf[wid * WCAP + p] = key;
                    }
                }
                vmL = vmC; vmC = vmN; ctrC = ctrN;
            }

            __syncwarp();
            unsigned cnt = wcnt[wid];
            if (cnt >= 128u) {                          // warp-scoped batched flush
                cnt = min(cnt, (unsigned)WCAP);
                unsigned base;
                if (lane == 0) base = atomicAdd(&g_count[b], cnt);
                base = __shfl_sync(0xFFFFFFFFu, base, 0);
                for (unsigned i = lane; i < cnt; i += 32) {
                    unsigned pos = base + i;
                    if (pos < CAP) g_cand[b][pos] = wbuf[wid * WCAP + i];
                }
                __syncwarp();
                if (lane == 0) wcnt[wid] = 0u;
                __syncwarp();
            }
        }

        // residual flush for this tile's batch (wbuf must not mix batches)
        __syncwarp();
        unsigned cnt = min(wcnt[wid], (unsigned)WCAP);
        if (cnt > 0u) {
            unsigned base;
            if (lane == 0) base = atomicAdd(&g_count[b], cnt);
            base = __shfl_sync(0xFFFFFFFFu, base, 0);
            for (unsigned i = lane; i < cnt; i += 32) {
                unsigned pos = base + i;
                if (pos < CAP) g_cand[b][pos] = wbuf[wid * WCAP + i];
            }
            __syncwarp();
            if (lane == 0) wcnt[wid] = 0u;
            __syncwarp();
        }
    }

    // ================= GLOBAL BARRIER =========================================
    __threadfence();
    __syncthreads();
    if (tid == 0) {
        atomicAdd(&g_arrive, 1u);
        while (*(volatile unsigned*)&g_arrive < (unsigned)NBLK) __nanosleep(64);
        __threadfence();
    }
    __syncthreads();

    // ================= PHASE 2: per-batch threshold + topk ====================
    if (blockIdx.x < NB) {
        const int b = blockIdx.x;
        for (int i = tid; i < NBINS2; i += THR) hist[i] = 0u;
        if (tid == 0) { s_cc = -1; s_above = 0u; s_n = 0; }
        __syncthreads();

        unsigned cnt = g_count[b]; if (cnt > CAP) cnt = CAP;
        for (unsigned i0 = tid; i0 < cnt; i0 += THR * 4) {
            #pragma unroll
            for (int u = 0; u < 4; u++) {
                unsigned i = i0 + (unsigned)u * THR;
                if (i < cnt) {
                    unsigned long long key = g_cand[b][i];
                    atomicAdd(&hist[(unsigned)(key >> 39)], 1u);  // top 14 bits of mapped... (mapped>>18)
                }
            }
        }
        __syncthreads();

        if (tid < 256) {
            unsigned s = 0;
            const uint4* hp = (const uint4*)&hist[tid * 64];
            #pragma unroll
            for (int k = 0; k < 16; k++) {
                uint4 v = hp[k]; s += v.x + v.y + v.z + v.w;
            }
            csA[tid] = s;
        }
        __syncthreads();
        unsigned *src = csA, *dst = csB;
        for (int st = 1; st < 256; st <<= 1) {            // inclusive suffix scan
            if (tid < 256) {
                unsigned v = src[tid];
                if (tid + st < 256) v += src[tid + st];
                dst[tid] = v;
            }
            __syncthreads();
            unsigned* t = src; src = dst; dst = t;
        }
        if (tid < 256 && src[tid] >= (unsigned)KTOP &&
            (tid == 255 || src[tid + 1] < (unsigned)KTOP)) {
            s_cc = tid;
            s_above = (tid == 255) ? 0u : src[tid + 1];
        }
        __syncthreads();
        if (tid == 0) {
            unsigned T = 0;
            if (s_cc >= 0) {
                unsigned acc = s_above;
                for (int bin = s_cc * 64 + 63; bin >= s_cc * 64; bin--) {
                    acc += hist[bin];
                    if (acc >= (unsigned)KTOP) { T = (unsigned)bin; break; }
                }
            }
            if (T > 0) T -= 1;        // one-bin margin for fp32 sigmoid collisions
            s_T = T;
        }
        __syncthreads();

        const unsigned thr = s_T << 18;
        for (unsigned i0 = tid; i0 < cnt; i0 += THR * 4) {
            #pragma unroll
            for (int u = 0; u < 4; u++) {
                unsigned i = i0 + (unsigned)u * THR;
                if (i < cnt) {
                    unsigned long long key = g_cand[b][i];
                    unsigned mapped = (unsigned)(key >> 21);
                    if (mapped >= thr) {
                        unsigned bits = (mapped & 0x80000000u)
                                      ? (mapped ^ 0x80000000u) : ~mapped;
                        float raw = __uint_as_float(bits);
                        float sg  = 1.0f / (1.0f + expf(-raw));
                        int p = atomicAdd(&s_n, 1);
                        if (p < SORTN)
                            sel[p] = ((unsigned long long)__float_as_uint(sg) << 21)
                                   | (key & 0x1FFFFFull);
                    }
                }
            }
        }
        __syncthreads();
        int n = s_n; if (n > SORTN) n = SORTN;
        for (int i = tid; i < SORTN; i += THR) if (i >= n) sel[i] = 0ull;

        for (unsigned ksz = 2; ksz <= (unsigned)SORTN; ksz <<= 1)
            for (unsigned j = ksz >> 1; j > 0; j >>= 1) {
                __syncthreads();
                for (unsigned i = tid; i < (unsigned)SORTN; i += THR) {
                    unsigned ixj = i ^ j;
                    if (ixj > i) {
                        unsigned long long a = sel[i], q = sel[ixj];
                        bool desc = ((i & ksz) == 0);
                        if (desc ? (a < q) : (a > q)) { sel[i] = q; sel[ixj] = a; }
                    }
                }
            }
        __syncthreads();

        if (tid < KTOP) {
            unsigned long long key = sel[tid];
            float score = 0.0f; unsigned idx = 0u;
            if (tid < n) {
                score = __uint_as_float((unsigned)(key >> 21));
                idx   = 0x1FFFFFu - (unsigned)(key & 0x1FFFFFull);
            }
            unsigned cl = idx % CC;
            unsigned sp = idx / CC;
            unsigned xs = sp % WW;
            unsigned ys = sp / WW;
            const float* wh = det + (((size_t)b * HH + ys) * WW + xs) * CHN + CC;
            float w0 = wh[0], w1 = wh[1], w2 = wh[2], w3 = wh[3];
            float fy = (float)ys, fx = (float)xs;
            float* o = out + ((size_t)b * KTOP + tid) * 6;
            o[0] = (fy - w0) * 0.0078125f;
            o[1] = (fx - w1) * 0.0078125f;
            o[2] = (fy + w2) * 0.0078125f;
            o[3] = (fx + w3) * 0.0078125f;
            o[4] = (float)cl;
            o[5] = score;
        }
        if (tid == 0) g_count[b] = 0u;                 // clean for next replay
    }

    // ================= DONE protocol (reset counters for replay) ==============
    if (tid == 0) {
        unsigned od = atomicAdd(&g_done, 1u);
        if (od == (unsigned)(NBLK - 1)) {
            g_ticket = 0u; g_arrive = 0u;
            __threadfence();
            g_done = 0u;
        }
    }
}

extern "C" void kernel_launch(void* const* d_in, const int* in_sizes, int n_in,
                              void* d_out, int out_size) {
    const float* det = (const float*)d_in[0];
    float* out = (float*)d_out;
    (void)in_sizes; (void)n_in; (void)out_size;

    cudaFuncSetAttribute(fused_kernel,
                         cudaFuncAttributeMaxDynamicSharedMemorySize, DYNSMEM);
    fused_kernel<<<NBLK, THR, DYNSMEM>>>(det, out);
}